// round 13
// baseline (speedup 1.0000x reference)
#include <cuda_runtime.h>
#include <cuda_bf16.h>
#include <math.h>

#define MAXV    2000000
#define NMESH   4

// Scratch: Lx (3 comps) + row_sum packed as float4 per row. 32 MB.
__device__ float4 d_acc[MAXV];
// Padded gather table: (x, y, z, 0) so gathers are a single LDG.128.
__device__ float4 d_verts4[MAXV];
__device__ float  d_inv_nvpm[NMESH];

// ---------------------------------------------------------------------------
// Warp-cooperative lower_bound: first i in [0,v) with idx[i] >= val (v if none).
// ---------------------------------------------------------------------------
__device__ int warp_lower_bound(const int* __restrict__ idx, int v, int val,
                                unsigned lane) {
    int lo = 0, hi = v;
    while (hi - lo > 32) {
        int seg = (hi - lo) / 33;
        int p = lo + ((int)lane + 1) * seg;
        bool lt = (__ldg(idx + p) < val);
        unsigned bal = __ballot_sync(0xFFFFFFFFu, lt);
        int count = __popc(bal);
        int newlo = (count > 0)  ? (lo + count * seg + 1) : lo;
        int newhi = (count < 32) ? (lo + (count + 1) * seg) : hi;
        lo = newlo; hi = newhi;
    }
    int p = lo + (int)lane;
    bool ge = (p >= hi) || (__ldg(idx + p) >= val);
    unsigned bal = __ballot_sync(0xFFFFFFFFu, ge);
    if (bal == 0) return hi;
    return lo + __ffs(bal) - 1;
}

// ---------------------------------------------------------------------------
// Kernel 1: verts4 table + zero acc + zero out + mesh counts (warp search).
// ---------------------------------------------------------------------------
__global__ void prep_kernel(const float* __restrict__ verts,
                            const int*   __restrict__ mesh_idx,
                            float* __restrict__ out, int v) {
    __shared__ int s_b[NMESH + 1];
    if (blockIdx.x == 0) {
        int w = threadIdx.x >> 5;
        unsigned lane = threadIdx.x & 31;
        if (w >= 1 && w <= 3) {
            int r = warp_lower_bound(mesh_idx, v, w, lane);
            if (lane == 0) s_b[w] = r;
        }
        if (threadIdx.x == 0) { s_b[0] = 0; s_b[NMESH] = v; out[0] = 0.f; }
        __syncthreads();
        if (threadIdx.x < NMESH) {
            int cnt = s_b[threadIdx.x + 1] - s_b[threadIdx.x];
            d_inv_nvpm[threadIdx.x] = (cnt > 0) ? (1.f / (float)cnt) : 0.f;
        }
    }

    const float4 z = make_float4(0.f, 0.f, 0.f, 0.f);
    int stride = gridDim.x * blockDim.x;
    for (int i = blockIdx.x * blockDim.x + threadIdx.x; i < v; i += stride) {
        const float* p = verts + 3 * (long long)i;
        float4 q;
        q.x = __ldg(p + 0);
        q.y = __ldg(p + 1);
        q.z = __ldg(p + 2);
        q.w = 0.f;
        d_verts4[i] = q;
        d_acc[i] = z;
    }
}

// ---------------------------------------------------------------------------
// Kernel 2: COO scatter — PERSISTENT grid-stride, 4 nnz per iteration.
// 6 CTAs/SM: the validated configuration (passed R7/R8/R9/R11).
// ---------------------------------------------------------------------------
__device__ __forceinline__ void red_add_v4(float4* addr, float x, float y,
                                           float z, float w) {
    asm volatile("red.global.add.v4.f32 [%0], {%1, %2, %3, %4};"
                 :: "l"(addr), "f"(x), "f"(y), "f"(z), "f"(w)
                 : "memory");
}

__device__ __forceinline__ void scatter_one(float v, int r, int c) {
    float4 p = __ldg(&d_verts4[c]);
    red_add_v4(&d_acc[r], v * p.x, v * p.y, v * p.z, v);
}

__global__ void __launch_bounds__(256)
scatter_kernel(const float* __restrict__ vals,
               const int*   __restrict__ rows,
               const int*   __restrict__ cols,
               int nnz) {
    int nquads = nnz >> 2;
    int stride = gridDim.x * blockDim.x;
    for (int q = blockIdx.x * blockDim.x + threadIdx.x; q < nquads; q += stride) {
        int base = q * 4;
        float4 v = __ldcs(reinterpret_cast<const float4*>(vals + base));
        int4   r = __ldcs(reinterpret_cast<const int4*>(rows + base));
        int4   c = __ldcs(reinterpret_cast<const int4*>(cols + base));
        float4 p0 = __ldg(&d_verts4[c.x]);
        float4 p1 = __ldg(&d_verts4[c.y]);
        float4 p2 = __ldg(&d_verts4[c.z]);
        float4 p3 = __ldg(&d_verts4[c.w]);
        red_add_v4(&d_acc[r.x], v.x * p0.x, v.x * p0.y, v.x * p0.z, v.x);
        red_add_v4(&d_acc[r.y], v.y * p1.x, v.y * p1.y, v.y * p1.z, v.y);
        red_add_v4(&d_acc[r.z], v.z * p2.x, v.z * p2.y, v.z * p2.z, v.z);
        red_add_v4(&d_acc[r.w], v.w * p3.x, v.w * p3.y, v.w * p3.z, v.w);
    }
    // tail (nnz % 4)
    int tail_start = nquads * 4;
    int tid_global = blockIdx.x * blockDim.x + threadIdx.x;
    int i = tail_start + tid_global;
    if (i < nnz)
        scatter_one(__ldg(vals + i), __ldg(rows + i), __ldg(cols + i));
}

// ---------------------------------------------------------------------------
// Kernel 3: per-vertex loss + global reduction (READ-ONLY on d_acc).
// 512-thread blocks; 2 independent pair-iterations in flight per thread.
// ---------------------------------------------------------------------------
__device__ __forceinline__ float pair_term(const float* __restrict__ verts,
                                           const int*   __restrict__ mesh_idx,
                                           const float* __restrict__ coefs,
                                           int pair) {
    int i0 = pair * 2;
    float4 L0 = __ldcs(&d_acc[i0]);
    float4 L1 = __ldcs(&d_acc[i0 + 1]);
    const float2* vp = reinterpret_cast<const float2*>(verts + 6 * (long long)pair);
    float2 a = __ldcs(vp + 0);
    float2 b = __ldcs(vp + 1);
    float2 c = __ldcs(vp + 2);
    int2   mi = __ldcs(reinterpret_cast<const int2*>(mesh_idx + i0));
    float2 cf = __ldcs(reinterpret_cast<const float2*>(coefs + i0));

    float nw0 = (L0.w > 0.f) ? (1.f / L0.w) : L0.w;
    float nw1 = (L1.w > 0.f) ? (1.f / L1.w) : L1.w;
    float rx0 = L0.x * nw0 - a.x, ry0 = L0.y * nw0 - a.y, rz0 = L0.z * nw0 - b.x;
    float rx1 = L1.x * nw1 - b.y, ry1 = L1.y * nw1 - c.x, rz1 = L1.z * nw1 - c.y;
    float l0 = sqrtf(rx0 * rx0 + ry0 * ry0 + rz0 * rz0);
    float l1 = sqrtf(rx1 * rx1 + ry1 * ry1 + rz1 * rz1);
    return l0 * d_inv_nvpm[mi.x] * cf.x + l1 * d_inv_nvpm[mi.y] * cf.y;
}

__global__ void __launch_bounds__(512)
finalize_kernel(const float* __restrict__ verts,
                const int*   __restrict__ mesh_idx,
                const float* __restrict__ coefs,
                float* __restrict__ out,
                int v) {
    int npairs = v >> 1;
    int t = blockIdx.x * blockDim.x + threadIdx.x;
    int stride = gridDim.x * blockDim.x;
    float acc = 0.f;

    int p0 = t;
    int p1 = t + stride;
    if (p1 < npairs) {
        acc = pair_term(verts, mesh_idx, coefs, p0)
            + pair_term(verts, mesh_idx, coefs, p1);
    } else if (p0 < npairs) {
        acc = pair_term(verts, mesh_idx, coefs, p0);
    }
    acc *= (1.f / (float)NMESH);

    // odd-v tail element
    if (t == 0 && (v & 1)) {
        int i = v - 1;
        float4 L = __ldg(&d_acc[i]);
        float nw = (L.w > 0.f) ? (1.f / L.w) : L.w;
        const float* p = verts + 3 * (long long)i;
        float rx = L.x * nw - __ldg(p + 0);
        float ry = L.y * nw - __ldg(p + 1);
        float rz = L.z * nw - __ldg(p + 2);
        acc += sqrtf(rx * rx + ry * ry + rz * rz)
               * d_inv_nvpm[__ldg(mesh_idx + i)] * __ldg(coefs + i)
               * (1.f / (float)NMESH);
    }

    // warp reduce
    #pragma unroll
    for (int off = 16; off > 0; off >>= 1)
        acc += __shfl_down_sync(0xFFFFFFFFu, acc, off);

    __shared__ float sdata[32];
    int lane = threadIdx.x & 31;
    int wid  = threadIdx.x >> 5;
    if (lane == 0) sdata[wid] = acc;
    __syncthreads();

    int nwarps = blockDim.x >> 5;
    if (wid == 0) {
        acc = (lane < nwarps) ? sdata[lane] : 0.f;
        #pragma unroll
        for (int off = 16; off > 0; off >>= 1)
            acc += __shfl_down_sync(0xFFFFFFFFu, acc, off);
        if (lane == 0)
            atomicAdd(out, acc);
    }
}

// ---------------------------------------------------------------------------
// Launch
// ---------------------------------------------------------------------------
extern "C" void kernel_launch(void* const* d_in, const int* in_sizes, int n_in,
                              void* d_out, int out_size) {
    const float* verts    = (const float*)d_in[0];
    const float* lap_vals = (const float*)d_in[1];
    const int*   lap_rows = (const int*)  d_in[2];
    const int*   lap_cols = (const int*)  d_in[3];
    const int*   mesh_idx = (const int*)  d_in[4];
    const float* coefs    = (const float*)d_in[5];
    float*       out      = (float*)d_out;

    int nnz = in_sizes[1];
    int v   = in_sizes[4];

    // 1. prep
    {
        int threads = 256;
        int blocks = (v + threads - 1) / threads;
        if (blocks > 8192) blocks = 8192;
        prep_kernel<<<blocks, threads>>>(verts, mesh_idx, out, v);
    }

    // 2. scatter — persistent grid-stride, 6 CTAs/SM (validated config)
    {
        int threads = 256;
        int blocks = 148 * 6;
        scatter_kernel<<<blocks, threads>>>(lap_vals, lap_rows, lap_cols, nnz);
    }

    // 3. finalize — 512 threads, 2 pair-iterations per thread
    {
        int threads = 512;
        int npairs = v >> 1;
        int total_threads = (npairs + 1) / 2;
        int blocks = (total_threads + threads - 1) / threads;
        if (blocks < 1) blocks = 1;
        finalize_kernel<<<blocks, threads>>>(verts, mesh_idx, coefs, out, v);
    }
}

// round 14
// speedup vs baseline: 1.0092x; 1.0092x over previous
#include <cuda_runtime.h>
#include <cuda_bf16.h>
#include <math.h>

#define MAXV    2000000
#define NMESH   4

// Scratch: Lx (3 comps) + row_sum packed as float4 per row. 32 MB.
__device__ float4 d_acc[MAXV];
// Padded gather table: (x, y, z, 0) so gathers are a single LDG.128.
__device__ float4 d_verts4[MAXV];
__device__ float  d_inv_nvpm[NMESH];

// ---------------------------------------------------------------------------
// Warp-cooperative lower_bound: first i in [0,v) with idx[i] >= val (v if none).
// ---------------------------------------------------------------------------
__device__ int warp_lower_bound(const int* __restrict__ idx, int v, int val,
                                unsigned lane) {
    int lo = 0, hi = v;
    while (hi - lo > 32) {
        int seg = (hi - lo) / 33;
        int p = lo + ((int)lane + 1) * seg;
        bool lt = (__ldg(idx + p) < val);
        unsigned bal = __ballot_sync(0xFFFFFFFFu, lt);
        int count = __popc(bal);
        int newlo = (count > 0)  ? (lo + count * seg + 1) : lo;
        int newhi = (count < 32) ? (lo + (count + 1) * seg) : hi;
        lo = newlo; hi = newhi;
    }
    int p = lo + (int)lane;
    bool ge = (p >= hi) || (__ldg(idx + p) >= val);
    unsigned bal = __ballot_sync(0xFFFFFFFFu, ge);
    if (bal == 0) return hi;
    return lo + __ffs(bal) - 1;
}

// ---------------------------------------------------------------------------
// Kernel 1: verts4 table + zero acc + zero out + mesh counts (warp search).
// ---------------------------------------------------------------------------
__global__ void prep_kernel(const float* __restrict__ verts,
                            const int*   __restrict__ mesh_idx,
                            float* __restrict__ out, int v) {
    __shared__ int s_b[NMESH + 1];
    if (blockIdx.x == 0) {
        int w = threadIdx.x >> 5;
        unsigned lane = threadIdx.x & 31;
        if (w >= 1 && w <= 3) {
            int r = warp_lower_bound(mesh_idx, v, w, lane);
            if (lane == 0) s_b[w] = r;
        }
        if (threadIdx.x == 0) { s_b[0] = 0; s_b[NMESH] = v; out[0] = 0.f; }
        __syncthreads();
        if (threadIdx.x < NMESH) {
            int cnt = s_b[threadIdx.x + 1] - s_b[threadIdx.x];
            d_inv_nvpm[threadIdx.x] = (cnt > 0) ? (1.f / (float)cnt) : 0.f;
        }
    }

    const float4 z = make_float4(0.f, 0.f, 0.f, 0.f);
    int stride = gridDim.x * blockDim.x;
    for (int i = blockIdx.x * blockDim.x + threadIdx.x; i < v; i += stride) {
        const float* p = verts + 3 * (long long)i;
        float4 q;
        q.x = __ldcs(p + 0);
        q.y = __ldcs(p + 1);
        q.z = __ldcs(p + 2);
        q.w = 0.f;
        d_verts4[i] = q;
        d_acc[i] = z;
    }
}

// ---------------------------------------------------------------------------
// Kernel 2: COO scatter — PERSISTENT grid-stride, 4 nnz per iteration,
// 6 CTAs/SM. DO NOT change this schedule: it is the validated config
// (5 passing runs); schedule changes re-roll the atomic-ordering rel_err.
// ---------------------------------------------------------------------------
__device__ __forceinline__ void red_add_v4(float4* addr, float x, float y,
                                           float z, float w) {
    asm volatile("red.global.add.v4.f32 [%0], {%1, %2, %3, %4};"
                 :: "l"(addr), "f"(x), "f"(y), "f"(z), "f"(w)
                 : "memory");
}

__device__ __forceinline__ void scatter_one(float v, int r, int c) {
    float4 p = __ldg(&d_verts4[c]);
    red_add_v4(&d_acc[r], v * p.x, v * p.y, v * p.z, v);
}

__global__ void __launch_bounds__(256)
scatter_kernel(const float* __restrict__ vals,
               const int*   __restrict__ rows,
               const int*   __restrict__ cols,
               int nnz) {
    int nquads = nnz >> 2;
    int stride = gridDim.x * blockDim.x;
    for (int q = blockIdx.x * blockDim.x + threadIdx.x; q < nquads; q += stride) {
        int base = q * 4;
        float4 v = __ldcs(reinterpret_cast<const float4*>(vals + base));
        int4   r = __ldcs(reinterpret_cast<const int4*>(rows + base));
        int4   c = __ldcs(reinterpret_cast<const int4*>(cols + base));
        float4 p0 = __ldg(&d_verts4[c.x]);
        float4 p1 = __ldg(&d_verts4[c.y]);
        float4 p2 = __ldg(&d_verts4[c.z]);
        float4 p3 = __ldg(&d_verts4[c.w]);
        red_add_v4(&d_acc[r.x], v.x * p0.x, v.x * p0.y, v.x * p0.z, v.x);
        red_add_v4(&d_acc[r.y], v.y * p1.x, v.y * p1.y, v.y * p1.z, v.y);
        red_add_v4(&d_acc[r.z], v.z * p2.x, v.z * p2.y, v.z * p2.z, v.z);
        red_add_v4(&d_acc[r.w], v.w * p3.x, v.w * p3.y, v.w * p3.z, v.w);
    }
    // tail (nnz % 4)
    int tail_start = nquads * 4;
    int tid_global = blockIdx.x * blockDim.x + threadIdx.x;
    int i = tail_start + tid_global;
    if (i < nnz)
        scatter_one(__ldg(vals + i), __ldg(rows + i), __ldg(cols + i));
}

// ---------------------------------------------------------------------------
// Kernel 3: per-vertex loss + global reduction (READ-ONLY on d_acc).
// 2 vertices per thread (R11-proven).
// ---------------------------------------------------------------------------
__global__ void __launch_bounds__(256)
finalize_kernel(const float* __restrict__ verts,
                const int*   __restrict__ mesh_idx,
                const float* __restrict__ coefs,
                float* __restrict__ out,
                int v) {
    int t = blockIdx.x * blockDim.x + threadIdx.x;
    int i0 = t * 2;
    float acc = 0.f;
    if (i0 + 1 < v) {
        float4 L0 = __ldcs(&d_acc[i0]);
        float4 L1 = __ldcs(&d_acc[i0 + 1]);
        const float2* vp = reinterpret_cast<const float2*>(verts + 6 * (long long)t);
        float2 a = __ldcs(vp + 0);   // v0.x v0.y
        float2 b = __ldcs(vp + 1);   // v0.z v1.x
        float2 c = __ldcs(vp + 2);   // v1.y v1.z
        int2   mi = __ldcs(reinterpret_cast<const int2*>(mesh_idx + i0));
        float2 cf = __ldcs(reinterpret_cast<const float2*>(coefs + i0));

        float nw0 = (L0.w > 0.f) ? (1.f / L0.w) : L0.w;
        float nw1 = (L1.w > 0.f) ? (1.f / L1.w) : L1.w;
        float rx0 = L0.x * nw0 - a.x, ry0 = L0.y * nw0 - a.y, rz0 = L0.z * nw0 - b.x;
        float rx1 = L1.x * nw1 - b.y, ry1 = L1.y * nw1 - c.x, rz1 = L1.z * nw1 - c.y;
        float l0 = sqrtf(rx0 * rx0 + ry0 * ry0 + rz0 * rz0);
        float l1 = sqrtf(rx1 * rx1 + ry1 * ry1 + rz1 * rz1);
        acc = (l0 * d_inv_nvpm[mi.x] * cf.x + l1 * d_inv_nvpm[mi.y] * cf.y)
              * (1.f / (float)NMESH);
    } else {
        for (int i = i0; i < v; i++) {
            float4 L = __ldg(&d_acc[i]);
            float nw = (L.w > 0.f) ? (1.f / L.w) : L.w;
            const float* p = verts + 3 * (long long)i;
            float rx = L.x * nw - __ldg(p + 0);
            float ry = L.y * nw - __ldg(p + 1);
            float rz = L.z * nw - __ldg(p + 2);
            float loss = sqrtf(rx * rx + ry * ry + rz * rz);
            acc += loss * d_inv_nvpm[__ldg(mesh_idx + i)] * __ldg(coefs + i)
                   * (1.f / (float)NMESH);
        }
    }

    // warp reduce
    #pragma unroll
    for (int off = 16; off > 0; off >>= 1)
        acc += __shfl_down_sync(0xFFFFFFFFu, acc, off);

    __shared__ float sdata[32];
    int lane = threadIdx.x & 31;
    int wid  = threadIdx.x >> 5;
    if (lane == 0) sdata[wid] = acc;
    __syncthreads();

    int nwarps = blockDim.x >> 5;
    if (wid == 0) {
        acc = (lane < nwarps) ? sdata[lane] : 0.f;
        #pragma unroll
        for (int off = 16; off > 0; off >>= 1)
            acc += __shfl_down_sync(0xFFFFFFFFu, acc, off);
        if (lane == 0)
            atomicAdd(out, acc);
    }
}

// ---------------------------------------------------------------------------
// Launch
// ---------------------------------------------------------------------------
extern "C" void kernel_launch(void* const* d_in, const int* in_sizes, int n_in,
                              void* d_out, int out_size) {
    const float* verts    = (const float*)d_in[0];
    const float* lap_vals = (const float*)d_in[1];
    const int*   lap_rows = (const int*)  d_in[2];
    const int*   lap_cols = (const int*)  d_in[3];
    const int*   mesh_idx = (const int*)  d_in[4];
    const float* coefs    = (const float*)d_in[5];
    float*       out      = (float*)d_out;

    int nnz = in_sizes[1];
    int v   = in_sizes[4];

    // 1. prep
    {
        int threads = 256;
        int blocks = (v + threads - 1) / threads;
        if (blocks > 8192) blocks = 8192;
        prep_kernel<<<blocks, threads>>>(verts, mesh_idx, out, v);
    }

    // 2. scatter — persistent grid-stride, 6 CTAs/SM (validated config)
    {
        int threads = 256;
        int blocks = 148 * 6;
        scatter_kernel<<<blocks, threads>>>(lap_vals, lap_rows, lap_cols, nnz);
    }

    // 3. finalize — 256 threads, 2 verts/thread (R11-proven)
    {
        int threads = 256;
        int pairs = (v + 1) / 2;
        int blocks = (pairs + threads - 1) / threads;
        finalize_kernel<<<blocks, threads>>>(verts, mesh_idx, coefs, out, v);
    }
}

// round 15
// speedup vs baseline: 1.0143x; 1.0051x over previous
#include <cuda_runtime.h>
#include <cuda_bf16.h>
#include <math.h>

#define MAXV    2000000
#define NMESH   4

// Scratch: Lx (3 comps) + row_sum packed as float4 per row. 32 MB.
__device__ float4 d_acc[MAXV];
// Padded gather table: (x, y, z, 0) so gathers are a single LDG.128.
__device__ float4 d_verts4[MAXV];
__device__ float  d_inv_nvpm[NMESH];
__device__ int    d_bounds[NMESH - 1];   // lower_bound(1), lb(2), lb(3)

// ---------------------------------------------------------------------------
// Warp-cooperative lower_bound: first i in [0,v) with idx[i] >= val (v if none).
// ---------------------------------------------------------------------------
__device__ int warp_lower_bound(const int* __restrict__ idx, int v, int val,
                                unsigned lane) {
    int lo = 0, hi = v;
    while (hi - lo > 32) {
        int seg = (hi - lo) / 33;
        int p = lo + ((int)lane + 1) * seg;
        bool lt = (__ldg(idx + p) < val);
        unsigned bal = __ballot_sync(0xFFFFFFFFu, lt);
        int count = __popc(bal);
        int newlo = (count > 0)  ? (lo + count * seg + 1) : lo;
        int newhi = (count < 32) ? (lo + (count + 1) * seg) : hi;
        lo = newlo; hi = newhi;
    }
    int p = lo + (int)lane;
    bool ge = (p >= hi) || (__ldg(idx + p) >= val);
    unsigned bal = __ballot_sync(0xFFFFFFFFu, ge);
    if (bal == 0) return hi;
    return lo + __ffs(bal) - 1;
}

// ---------------------------------------------------------------------------
// Kernel 1: verts4 table + zero acc + zero out + mesh counts/bounds.
// ---------------------------------------------------------------------------
__global__ void prep_kernel(const float* __restrict__ verts,
                            const int*   __restrict__ mesh_idx,
                            float* __restrict__ out, int v) {
    __shared__ int s_b[NMESH + 1];
    if (blockIdx.x == 0) {
        int w = threadIdx.x >> 5;
        unsigned lane = threadIdx.x & 31;
        if (w >= 1 && w <= 3) {
            int r = warp_lower_bound(mesh_idx, v, w, lane);
            if (lane == 0) { s_b[w] = r; d_bounds[w - 1] = r; }
        }
        if (threadIdx.x == 0) { s_b[0] = 0; s_b[NMESH] = v; out[0] = 0.f; }
        __syncthreads();
        if (threadIdx.x < NMESH) {
            int cnt = s_b[threadIdx.x + 1] - s_b[threadIdx.x];
            d_inv_nvpm[threadIdx.x] = (cnt > 0) ? (1.f / (float)cnt) : 0.f;
        }
    }

    const float4 z = make_float4(0.f, 0.f, 0.f, 0.f);
    int stride = gridDim.x * blockDim.x;
    for (int i = blockIdx.x * blockDim.x + threadIdx.x; i < v; i += stride) {
        const float* p = verts + 3 * (long long)i;
        float4 q;
        q.x = __ldcs(p + 0);
        q.y = __ldcs(p + 1);
        q.z = __ldcs(p + 2);
        q.w = 0.f;
        d_verts4[i] = q;
        d_acc[i] = z;
    }
}

// ---------------------------------------------------------------------------
// Kernel 2: COO scatter — PERSISTENT grid-stride, 4 nnz per iteration,
// 6 CTAs/SM. DO NOT change this schedule: validated config (6 passing runs);
// schedule changes re-roll the atomic-ordering rel_err.
// ---------------------------------------------------------------------------
__device__ __forceinline__ void red_add_v4(float4* addr, float x, float y,
                                           float z, float w) {
    asm volatile("red.global.add.v4.f32 [%0], {%1, %2, %3, %4};"
                 :: "l"(addr), "f"(x), "f"(y), "f"(z), "f"(w)
                 : "memory");
}

__device__ __forceinline__ void scatter_one(float v, int r, int c) {
    float4 p = __ldg(&d_verts4[c]);
    red_add_v4(&d_acc[r], v * p.x, v * p.y, v * p.z, v);
}

__global__ void __launch_bounds__(256)
scatter_kernel(const float* __restrict__ vals,
               const int*   __restrict__ rows,
               const int*   __restrict__ cols,
               int nnz) {
    int nquads = nnz >> 2;
    int stride = gridDim.x * blockDim.x;
    for (int q = blockIdx.x * blockDim.x + threadIdx.x; q < nquads; q += stride) {
        int base = q * 4;
        float4 v = __ldcs(reinterpret_cast<const float4*>(vals + base));
        int4   r = __ldcs(reinterpret_cast<const int4*>(rows + base));
        int4   c = __ldcs(reinterpret_cast<const int4*>(cols + base));
        float4 p0 = __ldg(&d_verts4[c.x]);
        float4 p1 = __ldg(&d_verts4[c.y]);
        float4 p2 = __ldg(&d_verts4[c.z]);
        float4 p3 = __ldg(&d_verts4[c.w]);
        red_add_v4(&d_acc[r.x], v.x * p0.x, v.x * p0.y, v.x * p0.z, v.x);
        red_add_v4(&d_acc[r.y], v.y * p1.x, v.y * p1.y, v.y * p1.z, v.y);
        red_add_v4(&d_acc[r.z], v.z * p2.x, v.z * p2.y, v.z * p2.z, v.z);
        red_add_v4(&d_acc[r.w], v.w * p3.x, v.w * p3.y, v.w * p3.z, v.w);
    }
    // tail (nnz % 4)
    int tail_start = nquads * 4;
    int tid_global = blockIdx.x * blockDim.x + threadIdx.x;
    int i = tail_start + tid_global;
    if (i < nnz)
        scatter_one(__ldg(vals + i), __ldg(rows + i), __ldg(cols + i));
}

// ---------------------------------------------------------------------------
// Kernel 3: per-vertex loss + global reduction (READ-ONLY on d_acc).
// 2 vertices per thread; mesh id derived from sorted bounds (no mesh_idx load).
// ---------------------------------------------------------------------------
__global__ void __launch_bounds__(256)
finalize_kernel(const float* __restrict__ verts,
                const float* __restrict__ coefs,
                float* __restrict__ out,
                int v) {
    // broadcast bounds + weights (L2-hit scalar loads, uniform across block)
    int b1 = d_bounds[0], b2 = d_bounds[1], b3 = d_bounds[2];
    float w0 = d_inv_nvpm[0], w1 = d_inv_nvpm[1],
          w2 = d_inv_nvpm[2], w3 = d_inv_nvpm[3];

    int t = blockIdx.x * blockDim.x + threadIdx.x;
    int i0 = t * 2;
    float acc = 0.f;
    if (i0 + 1 < v) {
        float4 L0 = __ldcs(&d_acc[i0]);
        float4 L1 = __ldcs(&d_acc[i0 + 1]);
        const float2* vp = reinterpret_cast<const float2*>(verts + 6 * (long long)t);
        float2 a = __ldcs(vp + 0);   // v0.x v0.y
        float2 b = __ldcs(vp + 1);   // v0.z v1.x
        float2 c = __ldcs(vp + 2);   // v1.y v1.z
        float2 cf = __ldcs(reinterpret_cast<const float2*>(coefs + i0));

        int m0 = (i0 >= b1) + (i0 >= b2) + (i0 >= b3);
        int i1 = i0 + 1;
        int m1 = (i1 >= b1) + (i1 >= b2) + (i1 >= b3);
        float wm0 = (m0 == 0) ? w0 : (m0 == 1) ? w1 : (m0 == 2) ? w2 : w3;
        float wm1 = (m1 == 0) ? w0 : (m1 == 1) ? w1 : (m1 == 2) ? w2 : w3;

        float nw0 = (L0.w > 0.f) ? (1.f / L0.w) : L0.w;
        float nw1 = (L1.w > 0.f) ? (1.f / L1.w) : L1.w;
        float rx0 = L0.x * nw0 - a.x, ry0 = L0.y * nw0 - a.y, rz0 = L0.z * nw0 - b.x;
        float rx1 = L1.x * nw1 - b.y, ry1 = L1.y * nw1 - c.x, rz1 = L1.z * nw1 - c.y;
        float l0 = sqrtf(rx0 * rx0 + ry0 * ry0 + rz0 * rz0);
        float l1 = sqrtf(rx1 * rx1 + ry1 * ry1 + rz1 * rz1);
        acc = (l0 * wm0 * cf.x + l1 * wm1 * cf.y) * (1.f / (float)NMESH);
    } else {
        for (int i = i0; i < v; i++) {
            float4 L = __ldg(&d_acc[i]);
            float nw = (L.w > 0.f) ? (1.f / L.w) : L.w;
            const float* p = verts + 3 * (long long)i;
            float rx = L.x * nw - __ldg(p + 0);
            float ry = L.y * nw - __ldg(p + 1);
            float rz = L.z * nw - __ldg(p + 2);
            float loss = sqrtf(rx * rx + ry * ry + rz * rz);
            int m = (i >= b1) + (i >= b2) + (i >= b3);
            float wm = (m == 0) ? w0 : (m == 1) ? w1 : (m == 2) ? w2 : w3;
            acc += loss * wm * __ldg(coefs + i) * (1.f / (float)NMESH);
        }
    }

    // warp reduce
    #pragma unroll
    for (int off = 16; off > 0; off >>= 1)
        acc += __shfl_down_sync(0xFFFFFFFFu, acc, off);

    __shared__ float sdata[32];
    int lane = threadIdx.x & 31;
    int wid  = threadIdx.x >> 5;
    if (lane == 0) sdata[wid] = acc;
    __syncthreads();

    int nwarps = blockDim.x >> 5;
    if (wid == 0) {
        acc = (lane < nwarps) ? sdata[lane] : 0.f;
        #pragma unroll
        for (int off = 16; off > 0; off >>= 1)
            acc += __shfl_down_sync(0xFFFFFFFFu, acc, off);
        if (lane == 0)
            atomicAdd(out, acc);
    }
}

// ---------------------------------------------------------------------------
// Launch
// ---------------------------------------------------------------------------
extern "C" void kernel_launch(void* const* d_in, const int* in_sizes, int n_in,
                              void* d_out, int out_size) {
    const float* verts    = (const float*)d_in[0];
    const float* lap_vals = (const float*)d_in[1];
    const int*   lap_rows = (const int*)  d_in[2];
    const int*   lap_cols = (const int*)  d_in[3];
    const int*   mesh_idx = (const int*)  d_in[4];
    const float* coefs    = (const float*)d_in[5];
    float*       out      = (float*)d_out;

    int nnz = in_sizes[1];
    int v   = in_sizes[4];

    // 1. prep
    {
        int threads = 256;
        int blocks = (v + threads - 1) / threads;
        if (blocks > 8192) blocks = 8192;
        prep_kernel<<<blocks, threads>>>(verts, mesh_idx, out, v);
    }

    // 2. scatter — persistent grid-stride, 6 CTAs/SM (validated config)
    {
        int threads = 256;
        int blocks = 148 * 6;
        scatter_kernel<<<blocks, threads>>>(lap_vals, lap_rows, lap_cols, nnz);
    }

    // 3. finalize — 256 threads, 2 verts/thread, bounds-derived mesh id
    {
        int threads = 256;
        int pairs = (v + 1) / 2;
        int blocks = (pairs + threads - 1) / threads;
        finalize_kernel<<<blocks, threads>>>(verts, coefs, out, v);
    }
}